// round 15
// baseline (speedup 1.0000x reference)
#include <cuda_runtime.h>
#include <cuda_fp16.h>
#include <cstdint>
#include <cstddef>

// ----------------------------------------------------------------------------
// BlockCirculantLinear on GB300 (sm_103a; PTX target lacks 'a' => no tcgen05).
// FFT-domain formulation, fp16 mma.sync m16n8k16, Gauss 3-mult complex product
// (11 uniform K=512 GEMM jobs). R9: x4 thread coarsening of fftx/ifft to cover
// long-scoreboard latency (both were issue-bound at <45% DRAM).
//   A planes (g_X, 11 x 512): 0:X0 1:X4 2:X1r 3:X1i 4:X1s 5:X2r 6:X2i 7:X2s
//                             8:X3r 9:X3i 10:X3s        (Xs = Xr + Xi)
//   ifft: Rf = P1-P2, If = P3-P1-P2 (irfft scales folded into weights).
// ----------------------------------------------------------------------------

#define BM 128
#define BN 128
#define BK 64
#define NSTAGE 3
#define MDIM 8192
#define NB 512
#define THREADS 256
#define NJOBS 11

static constexpr int AK      = NJOBS * 512;          // 5632, g_X row stride
static constexpr int BK_ROW  = 512;                  // g_B row stride
static constexpr size_t PLANE = (size_t)MDIM * NB;

static constexpr int TILE_BYTES  = BM * BK * 2;          // 16384 (fp16)
static constexpr int STAGE_BYTES = 2 * TILE_BYTES;       // 32768
static constexpr int SMEM_TOTAL  = NSTAGE * STAGE_BYTES; // 98304 -> 2 CTAs/SM

__device__ __half g_X[(size_t)MDIM * AK];              // freq x (fp16)
__device__ __half g_B[(size_t)NJOBS * NB * BK_ROW];    // freq weights (fp16)
__device__ __half g_O[(size_t)NJOBS * PLANE];          // freq planes (fp16)

// ---------------- helpers ---------------------------------------------------

__device__ __forceinline__ uint32_t smem_u32(const void* p) {
    uint32_t a;
    asm("{ .reg .u64 t; cvta.to.shared.u64 t, %1; cvt.u32.u64 %0, t; }"
        : "=r"(a) : "l"(p));
    return a;
}

#define SWZ(off) ((off) ^ (((off) >> 3) & 0x70))

__device__ __forceinline__ void cp_async16(uint32_t dst, const void* src) {
    asm volatile("cp.async.cg.shared.global [%0], [%1], 16;" :: "r"(dst), "l"(src));
}
__device__ __forceinline__ void cp_commit() {
    asm volatile("cp.async.commit_group;" ::: "memory");
}
template <int N> __device__ __forceinline__ void cp_wait() {
    asm volatile("cp.async.wait_group %0;" :: "n"(N) : "memory");
}

__device__ __forceinline__ void ldsm4(uint32_t* r, uint32_t addr) {
    asm volatile("ldmatrix.sync.aligned.m8n8.x4.shared.b16 {%0,%1,%2,%3}, [%4];"
                 : "=r"(r[0]), "=r"(r[1]), "=r"(r[2]), "=r"(r[3]) : "r"(addr));
}

__device__ __forceinline__ void mma_f16(float* c, const uint32_t* a,
                                        uint32_t b0, uint32_t b1) {
    asm volatile(
        "mma.sync.aligned.m16n8k16.row.col.f32.f16.f16.f32 "
        "{%0,%1,%2,%3}, {%4,%5,%6,%7}, {%8,%9}, {%0,%1,%2,%3};"
        : "+f"(c[0]), "+f"(c[1]), "+f"(c[2]), "+f"(c[3])
        : "r"(a[0]), "r"(a[1]), "r"(a[2]), "r"(a[3]), "r"(b0), "r"(b1));
}

#define FFT8(x0,x1,x2,x3,x4,x5,x6,x7, R0,R4,R1,I1,R2,I2,R3,I3)                \
    {                                                                         \
        const float cc = 0.70710678118654752440f;                             \
        float s04 = (x0) + (x4), d04 = (x0) - (x4);                           \
        float s26 = (x2) + (x6), d26 = (x2) - (x6);                           \
        float s15 = (x1) + (x5), d15 = (x1) - (x5);                           \
        float s37 = (x3) + (x7), d37 = (x3) - (x7);                           \
        R0 = s04 + s26 + s15 + s37;                                           \
        R4 = s04 + s26 - s15 - s37;                                           \
        R2 = s04 - s26;                                                       \
        I2 = s37 - s15;                                                       \
        float e = cc * (d15 - d37), o = cc * (d15 + d37);                     \
        R1 = d04 + e;  I1 = -d26 - o;                                         \
        R3 = d04 - e;  I3 =  d26 - o;                                         \
    }

// ---------------- Kernel 1: x -> 11 freq planes (4 blocks / thread) ---------
__global__ void fftx_kernel(const float4* __restrict__ x4) {
    int t  = blockIdx.x * blockDim.x + threadIdx.x;  // MDIM*NB/4
    int m  = t >> 7;
    int ib = (t & 127) * 4;
    float v[4][11];
#pragma unroll
    for (int u = 0; u < 4; u++) {
        float4 a = x4[(size_t)m * 1024 + (ib + u) * 2];
        float4 b = x4[(size_t)m * 1024 + (ib + u) * 2 + 1];
        float R0, R4, R1, I1, R2, I2, R3, I3;
        FFT8(a.x, a.y, a.z, a.w, b.x, b.y, b.z, b.w,
             R0, R4, R1, I1, R2, I2, R3, I3);
        v[u][0] = R0;  v[u][1] = R4;
        v[u][2] = R1;  v[u][3] = I1;  v[u][4]  = R1 + I1;
        v[u][5] = R2;  v[u][6] = I2;  v[u][7]  = R2 + I2;
        v[u][8] = R3;  v[u][9] = I3;  v[u][10] = R3 + I3;
    }
    __half* p = g_X + (size_t)m * AK + ib;
#pragma unroll
    for (int pl = 0; pl < 11; pl++) {
        __half2 h01 = __floats2half2_rn(v[0][pl], v[1][pl]);
        __half2 h23 = __floats2half2_rn(v[2][pl], v[3][pl]);
        uint2 w;
        w.x = *(uint32_t*)&h01;
        w.y = *(uint32_t*)&h23;
        *(uint2*)(p + pl * 512) = w;
    }
}

// ---------------- Kernel 2: circ -> 11 freq weight matrices (scaled) --------
__global__ void fftc_kernel(const float* __restrict__ circ) {
    int t  = blockIdx.x * blockDim.x + threadIdx.x;  // NB*NB
    int nb = t >> 9;
    int ib = t & 511;
    const float* cp = circ + ((size_t)nb * NB + ib) * 8;
    float R0, R4, R1, I1, R2, I2, R3, I3;
    FFT8(cp[0], cp[1], cp[2], cp[3], cp[4], cp[5], cp[6], cp[7],
         R0, R4, R1, I1, R2, I2, R3, I3);
    float w[11];
    w[0] = R0 * 0.125f;  w[1] = R4 * 0.125f;
    w[2] = R1 * 0.25f;   w[3] = I1 * 0.25f;   w[4]  = (R1 + I1) * 0.25f;
    w[5] = R2 * 0.25f;   w[6] = I2 * 0.25f;   w[7]  = (R2 + I2) * 0.25f;
    w[8] = R3 * 0.25f;   w[9] = I3 * 0.25f;   w[10] = (R3 + I3) * 0.25f;
    const size_t JS = (size_t)NB * BK_ROW;
    __half* r = g_B + (size_t)nb * BK_ROW + ib;
#pragma unroll
    for (int j = 0; j < 11; j++) r[j * JS] = __float2half_rn(w[j]);
}

// ---------------- Kernel 3: batched FP16 mma.sync GEMM ----------------------
// 11 jobs x 64 m-tiles x 4 n-tiles, all K=512 (NKIT=8).
__global__ void __launch_bounds__(THREADS) bc_gemm() {
    extern __shared__ char smem[];
    uint32_t sb0 = smem_u32(smem);
    const int tid = threadIdx.x;
    const int wid = tid >> 5;
    const int lid = tid & 31;
    const int wm = (wid >> 2) * 64;
    const int wn = (wid & 3) * 32;

    const int job = blockIdx.x >> 8;                 // 256 CTAs per job
    const int rem = blockIdx.x & 255;
    const int m0 = (rem & 63) * BM;
    const int n0 = (rem >> 6) * BN;
    const int NKIT = 8;                              // K = 512, BK = 64

    const __half* Arow = g_X + (size_t)m0 * AK + job * 512;
    const __half* Brow = g_B + (size_t)job * NB * BK_ROW + (size_t)n0 * BK_ROW;

    auto load_stage = [&](int s, int kiter) {
        uint32_t stg = sb0 + s * STAGE_BYTES;
        int k0 = kiter * BK;
#pragma unroll
        for (int q = 0; q < 4; q++) {
            int idx = tid + q * THREADS;             // 0..1023 chunks of 16B
            int row = idx >> 3;
            int ch  = idx & 7;
            uint32_t sw = SWZ((uint32_t)(row * 128 + ch * 16));
            cp_async16(stg + sw,              Arow + (size_t)row * AK     + k0 + ch * 8);
            cp_async16(stg + TILE_BYTES + sw, Brow + (size_t)row * BK_ROW + k0 + ch * 8);
        }
        cp_commit();
    };

    float acc[4][4][4];
#pragma unroll
    for (int mf = 0; mf < 4; mf++)
#pragma unroll
        for (int nf = 0; nf < 4; nf++)
#pragma unroll
            for (int r = 0; r < 4; r++) acc[mf][nf][r] = 0.0f;

    load_stage(0, 0);
    load_stage(1, 1);

    const int lrow = lid & 15;
    const int lcol = (lid >> 4) * 16;

    for (int i = 0; i < NKIT; i++) {
        cp_wait<1>();
        __syncthreads();
        if (i + 2 < NKIT) load_stage((i + 2) % NSTAGE, i + 2);

        uint32_t Ab = sb0 + (i % NSTAGE) * STAGE_BYTES;
        uint32_t Bb = Ab + TILE_BYTES;

#pragma unroll
        for (int ks = 0; ks < 4; ks++) {             // 4 x k16 = BK 64
            uint32_t a[4][4];
#pragma unroll
            for (int mf = 0; mf < 4; mf++) {
                uint32_t off = (uint32_t)((wm + mf * 16 + lrow) * 128 + ks * 32 + lcol);
                ldsm4(a[mf], Ab + SWZ(off));
            }
            uint32_t b[2][4];
#pragma unroll
            for (int p = 0; p < 2; p++) {
                uint32_t off = (uint32_t)((wn + p * 16 + lrow) * 128 + ks * 32 + lcol);
                ldsm4(b[p], Bb + SWZ(off));
            }
#pragma unroll
            for (int mf = 0; mf < 4; mf++)
#pragma unroll
                for (int nf = 0; nf < 4; nf++) {
                    int p = nf >> 1, o = nf & 1;
                    mma_f16(acc[mf][nf], a[mf], b[p][o], b[p][2 + o]);
                }
        }
    }

    __half* O = g_O + (size_t)job * PLANE;
    const int crow = lid >> 2;
    const int ccol = 2 * (lid & 3);
#pragma unroll
    for (int nf = 0; nf < 4; nf++) {
        int col = n0 + wn + nf * 8 + ccol;
#pragma unroll
        for (int mf = 0; mf < 4; mf++) {
            int row = m0 + wm + mf * 16 + crow;
            *(__half2*)(O + (size_t)row * NB + col) =
                __floats2half2_rn(acc[mf][nf][0], acc[mf][nf][1]);
            *(__half2*)(O + (size_t)(row + 8) * NB + col) =
                __floats2half2_rn(acc[mf][nf][2], acc[mf][nf][3]);
        }
    }
}

// ---------------- Kernel 4: Gauss recombine + irfft + bias (4 blk/thread) ---
__global__ void ifft_kernel(const float* __restrict__ bias,
                            float* __restrict__ out) {
    int t  = blockIdx.x * blockDim.x + threadIdx.x;  // MDIM*NB/4
    int m  = t >> 7;
    int nb = (t & 127) * 4;
    const __half* p = g_O + (size_t)m * NB + nb;
    float2 q[11][2];
#pragma unroll
    for (int j = 0; j < 11; j++) {
        uint2 w = *(const uint2*)(p + j * PLANE);
        q[j][0] = __half22float2(*(__half2*)&w.x);
        q[j][1] = __half22float2(*(__half2*)&w.y);
    }

    const float cc = 0.70710678118654752440f;
#pragma unroll
    for (int u = 0; u < 4; u++) {
        int g = u >> 1, h = u & 1;
        float R0 = h ? q[0][g].y : q[0][g].x;
        float R4 = h ? q[1][g].y : q[1][g].x;
        float P1, P2, P3;
        P1 = h ? q[2][g].y : q[2][g].x;
        P2 = h ? q[3][g].y : q[3][g].x;
        P3 = h ? q[4][g].y : q[4][g].x;
        float R1 = P1 - P2, I1 = P3 - P1 - P2;
        P1 = h ? q[5][g].y : q[5][g].x;
        P2 = h ? q[6][g].y : q[6][g].x;
        P3 = h ? q[7][g].y : q[7][g].x;
        float R2 = P1 - P2, I2 = P3 - P1 - P2;
        P1 = h ? q[8][g].y : q[8][g].x;
        P2 = h ? q[9][g].y : q[9][g].x;
        P3 = h ? q[10][g].y : q[10][g].x;
        float R3 = P1 - P2, I3 = P3 - P1 - P2;

        float se = R0 + R4, so = R0 - R4;
        float y0 = se + R1 + R2 + R3;
        float y2 = se - I1 - R2 + I3;
        float y4 = se - R1 + R2 - R3;
        float y6 = se + I1 - R2 - I3;
        float a1 = cc * (R1 - I1), b1 = cc * (R1 + I1);
        float a3 = cc * (R3 - I3), b3 = cc * (R3 + I3);
        float y1 = so + a1 - I2 - b3;
        float y3 = so - b1 + I2 + a3;
        float y5 = so - a1 - I2 + b3;
        float y7 = so + b1 + I2 - a3;

        int nbh = nb + u;
        const float4 bv0 = *(const float4*)(bias + nbh * 8);
        const float4 bv1 = *(const float4*)(bias + nbh * 8 + 4);
        float4* dst = (float4*)(out + (size_t)m * 4096 + nbh * 8);
        dst[0] = make_float4(y0 + bv0.x, y1 + bv0.y, y2 + bv0.z, y3 + bv0.w);
        dst[1] = make_float4(y4 + bv1.x, y5 + bv1.y, y6 + bv1.z, y7 + bv1.w);
    }
}

// ---------------- Launch ----------------------------------------------------

extern "C" void kernel_launch(void* const* d_in, const int* in_sizes, int n_in,
                              void* d_out, int out_size) {
    const float* x    = (const float*)d_in[0];
    const float* circ = (const float*)d_in[1];
    const float* bias = (const float*)d_in[2];
    float* out = (float*)d_out;

    fftx_kernel<<<(MDIM * NB / 4) / 256, 256>>>((const float4*)x);
    fftc_kernel<<<(NB * NB) / 256, 256>>>(circ);

    cudaFuncSetAttribute(bc_gemm, cudaFuncAttributeMaxDynamicSharedMemorySize,
                         SMEM_TOTAL);
    bc_gemm<<<NJOBS * 64 * 4, THREADS, SMEM_TOTAL>>>();   // 2816 CTAs

    ifft_kernel<<<(MDIM * NB / 4) / 256, 256>>>(bias, out);
    (void)in_sizes; (void)n_in; (void)out_size;
}

// round 16
// speedup vs baseline: 1.6412x; 1.6412x over previous
#include <cuda_runtime.h>
#include <cuda_fp16.h>
#include <cstdint>
#include <cstddef>

// ----------------------------------------------------------------------------
// BlockCirculantLinear on GB300 (sm_103a; PTX target lacks 'a' => no tcgen05).
// FFT-domain formulation, fp16 mma.sync m16n8k16, Gauss 3-mult complex product
// (11 uniform K=512 GEMM jobs). R10: transforms reverted to R8's x2 coarsening
// (R9's x4 killed occupancy 87->42%); GEMM main loop fully unrolled so ptxas
// can software-pipeline LDSM/cp.async across ks/iteration boundaries.
//   A planes (g_X, 11 x 512): 0:X0 1:X4 2:X1r 3:X1i 4:X1s 5:X2r 6:X2i 7:X2s
//                             8:X3r 9:X3i 10:X3s        (Xs = Xr + Xi)
//   ifft: Rf = P1-P2, If = P3-P1-P2 (irfft scales folded into weights).
// ----------------------------------------------------------------------------

#define BM 128
#define BN 128
#define BK 64
#define NSTAGE 3
#define MDIM 8192
#define NB 512
#define THREADS 256
#define NJOBS 11
#define NKIT 8

static constexpr int AK      = NJOBS * 512;          // 5632, g_X row stride
static constexpr int BK_ROW  = 512;                  // g_B row stride
static constexpr size_t PLANE = (size_t)MDIM * NB;

static constexpr int TILE_BYTES  = BM * BK * 2;          // 16384 (fp16)
static constexpr int STAGE_BYTES = 2 * TILE_BYTES;       // 32768
static constexpr int SMEM_TOTAL  = NSTAGE * STAGE_BYTES; // 98304 -> 2 CTAs/SM

__device__ __half g_X[(size_t)MDIM * AK];              // freq x (fp16)
__device__ __half g_B[(size_t)NJOBS * NB * BK_ROW];    // freq weights (fp16)
__device__ __half g_O[(size_t)NJOBS * PLANE];          // freq planes (fp16)

// ---------------- helpers ---------------------------------------------------

__device__ __forceinline__ uint32_t smem_u32(const void* p) {
    uint32_t a;
    asm("{ .reg .u64 t; cvta.to.shared.u64 t, %1; cvt.u32.u64 %0, t; }"
        : "=r"(a) : "l"(p));
    return a;
}

#define SWZ(off) ((off) ^ (((off) >> 3) & 0x70))

__device__ __forceinline__ void cp_async16(uint32_t dst, const void* src) {
    asm volatile("cp.async.cg.shared.global [%0], [%1], 16;" :: "r"(dst), "l"(src));
}
__device__ __forceinline__ void cp_commit() {
    asm volatile("cp.async.commit_group;" ::: "memory");
}
template <int N> __device__ __forceinline__ void cp_wait() {
    asm volatile("cp.async.wait_group %0;" :: "n"(N) : "memory");
}

__device__ __forceinline__ void ldsm4(uint32_t* r, uint32_t addr) {
    asm volatile("ldmatrix.sync.aligned.m8n8.x4.shared.b16 {%0,%1,%2,%3}, [%4];"
                 : "=r"(r[0]), "=r"(r[1]), "=r"(r[2]), "=r"(r[3]) : "r"(addr));
}

__device__ __forceinline__ void mma_f16(float* c, const uint32_t* a,
                                        uint32_t b0, uint32_t b1) {
    asm volatile(
        "mma.sync.aligned.m16n8k16.row.col.f32.f16.f16.f32 "
        "{%0,%1,%2,%3}, {%4,%5,%6,%7}, {%8,%9}, {%0,%1,%2,%3};"
        : "+f"(c[0]), "+f"(c[1]), "+f"(c[2]), "+f"(c[3])
        : "r"(a[0]), "r"(a[1]), "r"(a[2]), "r"(a[3]), "r"(b0), "r"(b1));
}

#define FFT8(x0,x1,x2,x3,x4,x5,x6,x7, R0,R4,R1,I1,R2,I2,R3,I3)                \
    {                                                                         \
        const float cc = 0.70710678118654752440f;                             \
        float s04 = (x0) + (x4), d04 = (x0) - (x4);                           \
        float s26 = (x2) + (x6), d26 = (x2) - (x6);                           \
        float s15 = (x1) + (x5), d15 = (x1) - (x5);                           \
        float s37 = (x3) + (x7), d37 = (x3) - (x7);                           \
        R0 = s04 + s26 + s15 + s37;                                           \
        R4 = s04 + s26 - s15 - s37;                                           \
        R2 = s04 - s26;                                                       \
        I2 = s37 - s15;                                                       \
        float e = cc * (d15 - d37), o = cc * (d15 + d37);                     \
        R1 = d04 + e;  I1 = -d26 - o;                                         \
        R3 = d04 - e;  I3 =  d26 - o;                                         \
    }

// ---------------- Kernel 1: x -> 11 freq planes (fp16, half2 stores) --------
__global__ void fftx_kernel(const float4* __restrict__ x4) {
    int t  = blockIdx.x * blockDim.x + threadIdx.x;  // MDIM*NB/2
    int m  = t >> 8;
    int ib = (t & 255) * 2;
    float4 a0 = x4[(size_t)m * 1024 + ib * 2];
    float4 b0 = x4[(size_t)m * 1024 + ib * 2 + 1];
    float4 a1 = x4[(size_t)m * 1024 + ib * 2 + 2];
    float4 b1 = x4[(size_t)m * 1024 + ib * 2 + 3];
    float v[2][11];
    {
        float R0, R4, R1, I1, R2, I2, R3, I3;
        FFT8(a0.x, a0.y, a0.z, a0.w, b0.x, b0.y, b0.z, b0.w,
             R0, R4, R1, I1, R2, I2, R3, I3);
        v[0][0] = R0;  v[0][1] = R4;
        v[0][2] = R1;  v[0][3] = I1;  v[0][4]  = R1 + I1;
        v[0][5] = R2;  v[0][6] = I2;  v[0][7]  = R2 + I2;
        v[0][8] = R3;  v[0][9] = I3;  v[0][10] = R3 + I3;
    }
    {
        float R0, R4, R1, I1, R2, I2, R3, I3;
        FFT8(a1.x, a1.y, a1.z, a1.w, b1.x, b1.y, b1.z, b1.w,
             R0, R4, R1, I1, R2, I2, R3, I3);
        v[1][0] = R0;  v[1][1] = R4;
        v[1][2] = R1;  v[1][3] = I1;  v[1][4]  = R1 + I1;
        v[1][5] = R2;  v[1][6] = I2;  v[1][7]  = R2 + I2;
        v[1][8] = R3;  v[1][9] = I3;  v[1][10] = R3 + I3;
    }
    __half* p = g_X + (size_t)m * AK + ib;
#pragma unroll
    for (int pl = 0; pl < 11; pl++)
        *(__half2*)(p + pl * 512) = __floats2half2_rn(v[0][pl], v[1][pl]);
}

// ---------------- Kernel 2: circ -> 11 freq weight matrices (scaled) --------
__global__ void fftc_kernel(const float* __restrict__ circ) {
    int t  = blockIdx.x * blockDim.x + threadIdx.x;  // NB*NB
    int nb = t >> 9;
    int ib = t & 511;
    const float* cp = circ + ((size_t)nb * NB + ib) * 8;
    float R0, R4, R1, I1, R2, I2, R3, I3;
    FFT8(cp[0], cp[1], cp[2], cp[3], cp[4], cp[5], cp[6], cp[7],
         R0, R4, R1, I1, R2, I2, R3, I3);
    float w[11];
    w[0] = R0 * 0.125f;  w[1] = R4 * 0.125f;
    w[2] = R1 * 0.25f;   w[3] = I1 * 0.25f;   w[4]  = (R1 + I1) * 0.25f;
    w[5] = R2 * 0.25f;   w[6] = I2 * 0.25f;   w[7]  = (R2 + I2) * 0.25f;
    w[8] = R3 * 0.25f;   w[9] = I3 * 0.25f;   w[10] = (R3 + I3) * 0.25f;
    const size_t JS = (size_t)NB * BK_ROW;
    __half* r = g_B + (size_t)nb * BK_ROW + ib;
#pragma unroll
    for (int j = 0; j < 11; j++) r[j * JS] = __float2half_rn(w[j]);
}

// ---------------- Kernel 3: batched FP16 mma.sync GEMM ----------------------
// 11 jobs x 64 m-tiles x 4 n-tiles, all K=512 (NKIT=8), fully unrolled.
__global__ void __launch_bounds__(THREADS) bc_gemm() {
    extern __shared__ char smem[];
    uint32_t sb0 = smem_u32(smem);
    const int tid = threadIdx.x;
    const int wid = tid >> 5;
    const int lid = tid & 31;
    const int wm = (wid >> 2) * 64;
    const int wn = (wid & 3) * 32;

    const int job = blockIdx.x >> 8;                 // 256 CTAs per job
    const int rem = blockIdx.x & 255;
    const int m0 = (rem & 63) * BM;
    const int n0 = (rem >> 6) * BN;

    const __half* Arow = g_X + (size_t)m0 * AK + job * 512;
    const __half* Brow = g_B + (size_t)job * NB * BK_ROW + (size_t)n0 * BK_ROW;

    auto load_stage = [&](int s, int kiter) {
        uint32_t stg = sb0 + s * STAGE_BYTES;
        int k0 = kiter * BK;
#pragma unroll
        for (int q = 0; q < 4; q++) {
            int idx = tid + q * THREADS;             // 0..1023 chunks of 16B
            int row = idx >> 3;
            int ch  = idx & 7;
            uint32_t sw = SWZ((uint32_t)(row * 128 + ch * 16));
            cp_async16(stg + sw,              Arow + (size_t)row * AK     + k0 + ch * 8);
            cp_async16(stg + TILE_BYTES + sw, Brow + (size_t)row * BK_ROW + k0 + ch * 8);
        }
        cp_commit();
    };

    float acc[4][4][4];
#pragma unroll
    for (int mf = 0; mf < 4; mf++)
#pragma unroll
        for (int nf = 0; nf < 4; nf++)
#pragma unroll
            for (int r = 0; r < 4; r++) acc[mf][nf][r] = 0.0f;

    load_stage(0, 0);
    load_stage(1, 1);

    const int lrow = lid & 15;
    const int lcol = (lid >> 4) * 16;

#pragma unroll
    for (int i = 0; i < NKIT; i++) {
        cp_wait<1>();
        __syncthreads();
        if (i + 2 < NKIT) load_stage((i + 2) % NSTAGE, i + 2);

        uint32_t Ab = sb0 + (i % NSTAGE) * STAGE_BYTES;
        uint32_t Bb = Ab + TILE_BYTES;

#pragma unroll
        for (int ks = 0; ks < 4; ks++) {             // 4 x k16 = BK 64
            uint32_t a[4][4];
#pragma unroll
            for (int mf = 0; mf < 4; mf++) {
                uint32_t off = (uint32_t)((wm + mf * 16 + lrow) * 128 + ks * 32 + lcol);
                ldsm4(a[mf], Ab + SWZ(off));
            }
            uint32_t b[2][4];
#pragma unroll
            for (int p = 0; p < 2; p++) {
                uint32_t off = (uint32_t)((wn + p * 16 + lrow) * 128 + ks * 32 + lcol);
                ldsm4(b[p], Bb + SWZ(off));
            }
#pragma unroll
            for (int mf = 0; mf < 4; mf++)
#pragma unroll
                for (int nf = 0; nf < 4; nf++) {
                    int p = nf >> 1, o = nf & 1;
                    mma_f16(acc[mf][nf], a[mf], b[p][o], b[p][2 + o]);
                }
        }
    }

    __half* O = g_O + (size_t)job * PLANE;
    const int crow = lid >> 2;
    const int ccol = 2 * (lid & 3);
#pragma unroll
    for (int nf = 0; nf < 4; nf++) {
        int col = n0 + wn + nf * 8 + ccol;
#pragma unroll
        for (int mf = 0; mf < 4; mf++) {
            int row = m0 + wm + mf * 16 + crow;
            *(__half2*)(O + (size_t)row * NB + col) =
                __floats2half2_rn(acc[mf][nf][0], acc[mf][nf][1]);
            *(__half2*)(O + (size_t)(row + 8) * NB + col) =
                __floats2half2_rn(acc[mf][nf][2], acc[mf][nf][3]);
        }
    }
}

// ---------------- Kernel 4: Gauss recombine + inverse rfft + bias (half2) ---
__global__ void ifft_kernel(const float* __restrict__ bias,
                            float* __restrict__ out) {
    int t  = blockIdx.x * blockDim.x + threadIdx.x;  // MDIM*NB/2
    int m  = t >> 8;
    int nb = (t & 255) * 2;
    const __half* p = g_O + (size_t)m * NB + nb;
    float2 q[11];
#pragma unroll
    for (int j = 0; j < 11; j++)
        q[j] = __half22float2(*(const __half2*)(p + j * PLANE));

    const float cc = 0.70710678118654752440f;
#pragma unroll
    for (int h = 0; h < 2; h++) {
        float R0 = h ? q[0].y : q[0].x, R4 = h ? q[1].y : q[1].x;
        float P1, P2, P3;
        P1 = h ? q[2].y : q[2].x;  P2 = h ? q[3].y : q[3].x;  P3 = h ? q[4].y : q[4].x;
        float R1 = P1 - P2, I1 = P3 - P1 - P2;
        P1 = h ? q[5].y : q[5].x;  P2 = h ? q[6].y : q[6].x;  P3 = h ? q[7].y : q[7].x;
        float R2 = P1 - P2, I2 = P3 - P1 - P2;
        P1 = h ? q[8].y : q[8].x;  P2 = h ? q[9].y : q[9].x;  P3 = h ? q[10].y : q[10].x;
        float R3 = P1 - P2, I3 = P3 - P1 - P2;

        float se = R0 + R4, so = R0 - R4;
        float y0 = se + R1 + R2 + R3;
        float y2 = se - I1 - R2 + I3;
        float y4 = se - R1 + R2 - R3;
        float y6 = se + I1 - R2 - I3;
        float a1 = cc * (R1 - I1), b1 = cc * (R1 + I1);
        float a3 = cc * (R3 - I3), b3 = cc * (R3 + I3);
        float y1 = so + a1 - I2 - b3;
        float y3 = so - b1 + I2 + a3;
        float y5 = so - a1 - I2 + b3;
        float y7 = so + b1 + I2 - a3;

        int nbh = nb + h;
        const float4 bv0 = *(const float4*)(bias + nbh * 8);
        const float4 bv1 = *(const float4*)(bias + nbh * 8 + 4);
        float4* dst = (float4*)(out + (size_t)m * 4096 + nbh * 8);
        dst[0] = make_float4(y0 + bv0.x, y1 + bv0.y, y2 + bv0.z, y3 + bv0.w);
        dst[1] = make_float4(y4 + bv1.x, y5 + bv1.y, y6 + bv1.z, y7 + bv1.w);
    }
}

// ---------------- Launch ----------------------------------------------------

extern "C" void kernel_launch(void* const* d_in, const int* in_sizes, int n_in,
                              void* d_out, int out_size) {
    const float* x    = (const float*)d_in[0];
    const float* circ = (const float*)d_in[1];
    const float* bias = (const float*)d_in[2];
    float* out = (float*)d_out;

    fftx_kernel<<<(MDIM * NB / 2) / 256, 256>>>((const float4*)x);
    fftc_kernel<<<(NB * NB) / 256, 256>>>(circ);

    cudaFuncSetAttribute(bc_gemm, cudaFuncAttributeMaxDynamicSharedMemorySize,
                         SMEM_TOTAL);
    bc_gemm<<<NJOBS * 64 * 4, THREADS, SMEM_TOTAL>>>();   // 2816 CTAs

    ifft_kernel<<<(MDIM * NB / 2) / 256, 256>>>(bias, out);
    (void)in_sizes; (void)n_in; (void)out_size;
}

// round 17
// speedup vs baseline: 1.7246x; 1.0508x over previous
#include <cuda_runtime.h>
#include <cuda_fp16.h>
#include <cstdint>
#include <cstddef>

// ----------------------------------------------------------------------------
// BlockCirculantLinear on GB300 (sm_103a; PTX target lacks 'a' => no tcgen05).
// FFT-domain formulation, fp16 mma.sync m16n8k16, Gauss 3-mult complex product
// (11 uniform K=512 GEMM jobs). R11 = R8 config (best: 238us) + streaming
// cache hints on the single-touch g_O round trip / x read / out write, and
// __launch_bounds__(256,2) pinning the GEMM's 2-CTA/SM occupancy.
//   A planes (g_X, 11 x 512): 0:X0 1:X4 2:X1r 3:X1i 4:X1s 5:X2r 6:X2i 7:X2s
//                             8:X3r 9:X3i 10:X3s        (Xs = Xr + Xi)
//   ifft: Rf = P1-P2, If = P3-P1-P2 (irfft scales folded into weights).
// ----------------------------------------------------------------------------

#define BM 128
#define BN 128
#define BK 64
#define NSTAGE 3
#define MDIM 8192
#define NB 512
#define THREADS 256
#define NJOBS 11

static constexpr int AK      = NJOBS * 512;          // 5632, g_X row stride
static constexpr int BK_ROW  = 512;                  // g_B row stride
static constexpr size_t PLANE = (size_t)MDIM * NB;

static constexpr int TILE_BYTES  = BM * BK * 2;          // 16384 (fp16)
static constexpr int STAGE_BYTES = 2 * TILE_BYTES;       // 32768
static constexpr int SMEM_TOTAL  = NSTAGE * STAGE_BYTES; // 98304 -> 2 CTAs/SM

__device__ __half g_X[(size_t)MDIM * AK];              // freq x (fp16)
__device__ __half g_B[(size_t)NJOBS * NB * BK_ROW];    // freq weights (fp16)
__device__ __half g_O[(size_t)NJOBS * PLANE];          // freq planes (fp16)

// ---------------- helpers ---------------------------------------------------

__device__ __forceinline__ uint32_t smem_u32(const void* p) {
    uint32_t a;
    asm("{ .reg .u64 t; cvta.to.shared.u64 t, %1; cvt.u32.u64 %0, t; }"
        : "=r"(a) : "l"(p));
    return a;
}

#define SWZ(off) ((off) ^ (((off) >> 3) & 0x70))

__device__ __forceinline__ void cp_async16(uint32_t dst, const void* src) {
    asm volatile("cp.async.cg.shared.global [%0], [%1], 16;" :: "r"(dst), "l"(src));
}
__device__ __forceinline__ void cp_commit() {
    asm volatile("cp.async.commit_group;" ::: "memory");
}
template <int N> __device__ __forceinline__ void cp_wait() {
    asm volatile("cp.async.wait_group %0;" :: "n"(N) : "memory");
}

__device__ __forceinline__ void ldsm4(uint32_t* r, uint32_t addr) {
    asm volatile("ldmatrix.sync.aligned.m8n8.x4.shared.b16 {%0,%1,%2,%3}, [%4];"
                 : "=r"(r[0]), "=r"(r[1]), "=r"(r[2]), "=r"(r[3]) : "r"(addr));
}

__device__ __forceinline__ void mma_f16(float* c, const uint32_t* a,
                                        uint32_t b0, uint32_t b1) {
    asm volatile(
        "mma.sync.aligned.m16n8k16.row.col.f32.f16.f16.f32 "
        "{%0,%1,%2,%3}, {%4,%5,%6,%7}, {%8,%9}, {%0,%1,%2,%3};"
        : "+f"(c[0]), "+f"(c[1]), "+f"(c[2]), "+f"(c[3])
        : "r"(a[0]), "r"(a[1]), "r"(a[2]), "r"(a[3]), "r"(b0), "r"(b1));
}

__device__ __forceinline__ uint32_t ldcs_u32(const void* p) {
    uint32_t v;
    asm volatile("ld.global.cs.b32 %0, [%1];" : "=r"(v) : "l"(p));
    return v;
}
__device__ __forceinline__ void stcs_u32(void* p, uint32_t v) {
    asm volatile("st.global.cs.b32 [%0], %1;" :: "l"(p), "r"(v));
}
__device__ __forceinline__ float4 ldcs_f4(const void* p) {
    float4 v;
    asm volatile("ld.global.cs.v4.f32 {%0,%1,%2,%3}, [%4];"
                 : "=f"(v.x), "=f"(v.y), "=f"(v.z), "=f"(v.w) : "l"(p));
    return v;
}
__device__ __forceinline__ void stcs_f4(void* p, float4 v) {
    asm volatile("st.global.cs.v4.f32 [%0], {%1,%2,%3,%4};"
                 :: "l"(p), "f"(v.x), "f"(v.y), "f"(v.z), "f"(v.w));
}

#define FFT8(x0,x1,x2,x3,x4,x5,x6,x7, R0,R4,R1,I1,R2,I2,R3,I3)                \
    {                                                                         \
        const float cc = 0.70710678118654752440f;                             \
        float s04 = (x0) + (x4), d04 = (x0) - (x4);                           \
        float s26 = (x2) + (x6), d26 = (x2) - (x6);                           \
        float s15 = (x1) + (x5), d15 = (x1) - (x5);                           \
        float s37 = (x3) + (x7), d37 = (x3) - (x7);                           \
        R0 = s04 + s26 + s15 + s37;                                           \
        R4 = s04 + s26 - s15 - s37;                                           \
        R2 = s04 - s26;                                                       \
        I2 = s37 - s15;                                                       \
        float e = cc * (d15 - d37), o = cc * (d15 + d37);                     \
        R1 = d04 + e;  I1 = -d26 - o;                                         \
        R3 = d04 - e;  I3 =  d26 - o;                                         \
    }

// ---------------- Kernel 1: x -> 11 freq planes (fp16, half2 stores) --------
__global__ void fftx_kernel(const float4* __restrict__ x4) {
    int t  = blockIdx.x * blockDim.x + threadIdx.x;  // MDIM*NB/2
    int m  = t >> 8;
    int ib = (t & 255) * 2;
    float4 a0 = ldcs_f4(x4 + (size_t)m * 1024 + ib * 2);
    float4 b0 = ldcs_f4(x4 + (size_t)m * 1024 + ib * 2 + 1);
    float4 a1 = ldcs_f4(x4 + (size_t)m * 1024 + ib * 2 + 2);
    float4 b1 = ldcs_f4(x4 + (size_t)m * 1024 + ib * 2 + 3);
    float v[2][11];
    {
        float R0, R4, R1, I1, R2, I2, R3, I3;
        FFT8(a0.x, a0.y, a0.z, a0.w, b0.x, b0.y, b0.z, b0.w,
             R0, R4, R1, I1, R2, I2, R3, I3);
        v[0][0] = R0;  v[0][1] = R4;
        v[0][2] = R1;  v[0][3] = I1;  v[0][4]  = R1 + I1;
        v[0][5] = R2;  v[0][6] = I2;  v[0][7]  = R2 + I2;
        v[0][8] = R3;  v[0][9] = I3;  v[0][10] = R3 + I3;
    }
    {
        float R0, R4, R1, I1, R2, I2, R3, I3;
        FFT8(a1.x, a1.y, a1.z, a1.w, b1.x, b1.y, b1.z, b1.w,
             R0, R4, R1, I1, R2, I2, R3, I3);
        v[1][0] = R0;  v[1][1] = R4;
        v[1][2] = R1;  v[1][3] = I1;  v[1][4]  = R1 + I1;
        v[1][5] = R2;  v[1][6] = I2;  v[1][7]  = R2 + I2;
        v[1][8] = R3;  v[1][9] = I3;  v[1][10] = R3 + I3;
    }
    __half* p = g_X + (size_t)m * AK + ib;
#pragma unroll
    for (int pl = 0; pl < 11; pl++) {
        __half2 h = __floats2half2_rn(v[0][pl], v[1][pl]);
        *(__half2*)(p + pl * 512) = h;   // re-read soon by GEMM: default policy
    }
}

// ---------------- Kernel 2: circ -> 11 freq weight matrices (scaled) --------
__global__ void fftc_kernel(const float* __restrict__ circ) {
    int t  = blockIdx.x * blockDim.x + threadIdx.x;  // NB*NB
    int nb = t >> 9;
    int ib = t & 511;
    const float* cp = circ + ((size_t)nb * NB + ib) * 8;
    float R0, R4, R1, I1, R2, I2, R3, I3;
    FFT8(cp[0], cp[1], cp[2], cp[3], cp[4], cp[5], cp[6], cp[7],
         R0, R4, R1, I1, R2, I2, R3, I3);
    float w[11];
    w[0] = R0 * 0.125f;  w[1] = R4 * 0.125f;
    w[2] = R1 * 0.25f;   w[3] = I1 * 0.25f;   w[4]  = (R1 + I1) * 0.25f;
    w[5] = R2 * 0.25f;   w[6] = I2 * 0.25f;   w[7]  = (R2 + I2) * 0.25f;
    w[8] = R3 * 0.25f;   w[9] = I3 * 0.25f;   w[10] = (R3 + I3) * 0.25f;
    const size_t JS = (size_t)NB * BK_ROW;
    __half* r = g_B + (size_t)nb * BK_ROW + ib;
#pragma unroll
    for (int j = 0; j < 11; j++) r[j * JS] = __float2half_rn(w[j]);
}

// ---------------- Kernel 3: batched FP16 mma.sync GEMM ----------------------
// 11 jobs x 64 m-tiles x 4 n-tiles, all K=512 (NKIT=8), dynamic loop (R8).
__global__ void __launch_bounds__(THREADS, 2) bc_gemm() {
    extern __shared__ char smem[];
    uint32_t sb0 = smem_u32(smem);
    const int tid = threadIdx.x;
    const int wid = tid >> 5;
    const int lid = tid & 31;
    const int wm = (wid >> 2) * 64;
    const int wn = (wid & 3) * 32;

    const int job = blockIdx.x >> 8;                 // 256 CTAs per job
    const int rem = blockIdx.x & 255;
    const int m0 = (rem & 63) * BM;
    const int n0 = (rem >> 6) * BN;
    const int NKIT = 8;                              // K = 512, BK = 64

    const __half* Arow = g_X + (size_t)m0 * AK + job * 512;
    const __half* Brow = g_B + (size_t)job * NB * BK_ROW + (size_t)n0 * BK_ROW;

    auto load_stage = [&](int s, int kiter) {
        uint32_t stg = sb0 + s * STAGE_BYTES;
        int k0 = kiter * BK;
#pragma unroll
        for (int q = 0; q < 4; q++) {
            int idx = tid + q * THREADS;             // 0..1023 chunks of 16B
            int row = idx >> 3;
            int ch  = idx & 7;
            uint32_t sw = SWZ((uint32_t)(row * 128 + ch * 16));
            cp_async16(stg + sw,              Arow + (size_t)row * AK     + k0 + ch * 8);
            cp_async16(stg + TILE_BYTES + sw, Brow + (size_t)row * BK_ROW + k0 + ch * 8);
        }
        cp_commit();
    };

    float acc[4][4][4];
#pragma unroll
    for (int mf = 0; mf < 4; mf++)
#pragma unroll
        for (int nf = 0; nf < 4; nf++)
#pragma unroll
            for (int r = 0; r < 4; r++) acc[mf][nf][r] = 0.0f;

    load_stage(0, 0);
    load_stage(1, 1);

    const int lrow = lid & 15;
    const int lcol = (lid >> 4) * 16;

    for (int i = 0; i < NKIT; i++) {
        cp_wait<1>();
        __syncthreads();
        if (i + 2 < NKIT) load_stage((i + 2) % NSTAGE, i + 2);

        uint32_t Ab = sb0 + (i % NSTAGE) * STAGE_BYTES;
        uint32_t Bb = Ab + TILE_BYTES;

#pragma unroll
        for (int ks = 0; ks < 4; ks++) {             // 4 x k16 = BK 64
            uint32_t a[4][4];
#pragma unroll
            for (int mf = 0; mf < 4; mf++) {
                uint32_t off = (uint32_t)((wm + mf * 16 + lrow) * 128 + ks * 32 + lcol);
                ldsm4(a[mf], Ab + SWZ(off));
            }
            uint32_t b[2][4];
#pragma unroll
            for (int p = 0; p < 2; p++) {
                uint32_t off = (uint32_t)((wn + p * 16 + lrow) * 128 + ks * 32 + lcol);
                ldsm4(b[p], Bb + SWZ(off));
            }
#pragma unroll
            for (int mf = 0; mf < 4; mf++)
#pragma unroll
                for (int nf = 0; nf < 4; nf++) {
                    int p = nf >> 1, o = nf & 1;
                    mma_f16(acc[mf][nf], a[mf], b[p][o], b[p][2 + o]);
                }
        }
    }

    // Epilogue: streaming (evict-first) stores — g_O is single-touch and
    // exceeds L2; keep it from evicting A/B working set.
    __half* O = g_O + (size_t)job * PLANE;
    const int crow = lid >> 2;
    const int ccol = 2 * (lid & 3);
#pragma unroll
    for (int nf = 0; nf < 4; nf++) {
        int col = n0 + wn + nf * 8 + ccol;
#pragma unroll
        for (int mf = 0; mf < 4; mf++) {
            int row = m0 + wm + mf * 16 + crow;
            __half2 v0 = __floats2half2_rn(acc[mf][nf][0], acc[mf][nf][1]);
            __half2 v1 = __floats2half2_rn(acc[mf][nf][2], acc[mf][nf][3]);
            stcs_u32(O + (size_t)row * NB + col,       *(uint32_t*)&v0);
            stcs_u32(O + (size_t)(row + 8) * NB + col, *(uint32_t*)&v1);
        }
    }
}

// ---------------- Kernel 4: Gauss recombine + inverse rfft + bias (half2) ---
__global__ void ifft_kernel(const float* __restrict__ bias,
                            float* __restrict__ out) {
    int t  = blockIdx.x * blockDim.x + threadIdx.x;  // MDIM*NB/2
    int m  = t >> 8;
    int nb = (t & 255) * 2;
    const __half* p = g_O + (size_t)m * NB + nb;
    float2 q[11];
#pragma unroll
    for (int j = 0; j < 11; j++) {
        uint32_t w = ldcs_u32(p + j * PLANE);        // single-touch: streaming
        q[j] = __half22float2(*(__half2*)&w);
    }

    const float cc = 0.70710678118654752440f;
#pragma unroll
    for (int h = 0; h < 2; h++) {
        float R0 = h ? q[0].y : q[0].x, R4 = h ? q[1].y : q[1].x;
        float P1, P2, P3;
        P1 = h ? q[2].y : q[2].x;  P2 = h ? q[3].y : q[3].x;  P3 = h ? q[4].y : q[4].x;
        float R1 = P1 - P2, I1 = P3 - P1 - P2;
        P1 = h ? q[5].y : q[5].x;  P2 = h ? q[6].y : q[6].x;  P3 = h ? q[7].y : q[7].x;
        float R2 = P1 - P2, I2 = P3 - P1 - P2;
        P1 = h ? q[8].y : q[8].x;  P2 = h ? q[9].y : q[9].x;  P3 = h ? q[10].y : q[10].x;
        float R3 = P1 - P2, I3 = P3 - P1 - P2;

        float se = R0 + R4, so = R0 - R4;
        float y0 = se + R1 + R2 + R3;
        float y2 = se - I1 - R2 + I3;
        float y4 = se - R1 + R2 - R3;
        float y6 = se + I1 - R2 - I3;
        float a1 = cc * (R1 - I1), b1 = cc * (R1 + I1);
        float a3 = cc * (R3 - I3), b3 = cc * (R3 + I3);
        float y1 = so + a1 - I2 - b3;
        float y3 = so - b1 + I2 + a3;
        float y5 = so - a1 - I2 + b3;
        float y7 = so + b1 + I2 - a3;

        int nbh = nb + h;
        const float4 bv0 = *(const float4*)(bias + nbh * 8);
        const float4 bv1 = *(const float4*)(bias + nbh * 8 + 4);
        float* dst = out + (size_t)m * 4096 + nbh * 8;
        stcs_f4(dst,     make_float4(y0 + bv0.x, y1 + bv0.y, y2 + bv0.z, y3 + bv0.w));
        stcs_f4(dst + 4, make_float4(y4 + bv1.x, y5 + bv1.y, y6 + bv1.z, y7 + bv1.w));
    }
}

// ---------------- Launch ----------------------------------------------------

extern "C" void kernel_launch(void* const* d_in, const int* in_sizes, int n_in,
                              void* d_out, int out_size) {
    const float* x    = (const float*)d_in[0];
    const float* circ = (const float*)d_in[1];
    const float* bias = (const float*)d_in[2];
    float* out = (float*)d_out;

    fftx_kernel<<<(MDIM * NB / 2) / 256, 256>>>((const float4*)x);
    fftc_kernel<<<(NB * NB) / 256, 256>>>(circ);

    cudaFuncSetAttribute(bc_gemm, cudaFuncAttributeMaxDynamicSharedMemorySize,
                         SMEM_TOTAL);
    bc_gemm<<<NJOBS * 64 * 4, THREADS, SMEM_TOTAL>>>();   // 2816 CTAs

    ifft_kernel<<<(MDIM * NB / 2) / 256, 256>>>(bias, out);
    (void)in_sizes; (void)n_in; (void)out_size;
}